// round 4
// baseline (speedup 1.0000x reference)
#include <cuda_runtime.h>
#include <cuda_bf16.h>
#include <cstdint>

// out[b,s] = | prod_k cos((x[b,k]-sv[s,k])/2) |
//          = | prod_k ( cos(x_k/2)cos(sv_k/2) + sin(x_k/2)sin(sv_k/2) ) |
// Block: 64 rows x 256 cols. Thread: 4 cols x 16 rows.
// sv trig hoisted to registers; x trig loaded per-row as warp-broadcast LDS.
#define NB 4096
#define NS 4096

// ---------- packed f32x2 helpers ----------
__device__ __forceinline__ uint64_t pk2(float lo, float hi) {
    uint64_t r; asm("mov.b64 %0, {%1, %2};" : "=l"(r) : "f"(lo), "f"(hi)); return r;
}
__device__ __forceinline__ void upk2(uint64_t v, float& lo, float& hi) {
    asm("mov.b64 {%0, %1}, %2;" : "=f"(lo), "=f"(hi) : "l"(v));
}
__device__ __forceinline__ uint64_t mul2(uint64_t a, uint64_t b) {
    uint64_t r; asm("mul.rn.f32x2 %0, %1, %2;" : "=l"(r) : "l"(a), "l"(b)); return r;
}
__device__ __forceinline__ uint64_t fma2(uint64_t a, uint64_t b, uint64_t c) {
    uint64_t r; asm("fma.rn.f32x2 %0, %1, %2, %3;" : "=l"(r) : "l"(a), "l"(b), "l"(c)); return r;
}
__device__ __forceinline__ uint64_t abs2(uint64_t v) {
    asm("and.b64 %0, %0, 0x7FFFFFFF7FFFFFFF;" : "+l"(v)); return v;
}

__global__ __launch_bounds__(256) void qk_fused_kernel(
    const float* __restrict__ x,
    const float* __restrict__ sv,
    float* __restrict__ out)
{
    // Trig tables, flat [local_idx] = [row_or_col][k] float4 records.
    __shared__ __align__(16) float sxc[256];    // cos(x/2), 64 rows x 4k
    __shared__ __align__(16) float sxs[256];    // sin(x/2)
    __shared__ __align__(16) float ssc[1024];   // cos(sv/2), 256 cols x 4k
    __shared__ __align__(16) float sss[1024];   // sin(sv/2)

    const int b0 = blockIdx.y << 6;    // 64 rows per block
    const int s0 = blockIdx.x << 8;    // 256 cols per block
    const int t  = threadIdx.x;

    // ---- prologue: 5 sincos/thread, fully linear loads & stores ----
    {
        float sn, cs;
        __sincosf(x[b0 * 4 + t] * 0.5f, &sn, &cs);   // (row, k) = t
        sxc[t] = cs; sxs[t] = sn;

        const int svbase = s0 * 4;
#pragma unroll
        for (int q = 0; q < 4; q++) {
            __sincosf(sv[svbase + q * 256 + t] * 0.5f, &sn, &cs);
            ssc[q * 256 + t] = cs;
            sss[q * 256 + t] = sn;
        }
    }
    __syncthreads();

    const int cg = t & 63;   // column group: 4 cols starting at s0 + 4*cg
    const int rg = t >> 6;   // row group: 16 rows starting at b0 + 16*rg
    // NOTE: all 32 lanes of a warp share rg -> x-trig LDS are broadcasts.

    // ---- hoist sv trig for this thread's 4 columns (8 LDS.128) ----
    uint64_t sc01[4], sc23[4], sn01[4], sn23[4];
#pragma unroll
    for (int j = 0; j < 4; j++) {
        const int col = (cg << 2) + j;
        ulonglong2 c = *reinterpret_cast<const ulonglong2*>(&ssc[col << 2]);
        ulonglong2 s = *reinterpret_cast<const ulonglong2*>(&sss[col << 2]);
        sc01[j] = c.x; sc23[j] = c.y;
        sn01[j] = s.x; sn23[j] = s.y;
    }

    float* orow = out + (size_t)(b0 + (rg << 4)) * NS + (s0 + (cg << 2));

#pragma unroll 4
    for (int i = 0; i < 16; i++) {
        const int row = (rg << 4) + i;
        // warp-broadcast loads (all lanes same address)
        ulonglong2 xc = *reinterpret_cast<const ulonglong2*>(&sxc[row << 2]);
        ulonglong2 xs = *reinterpret_cast<const ulonglong2*>(&sxs[row << 2]);

        uint64_t p[4];
#pragma unroll
        for (int j = 0; j < 4; j++) {
            uint64_t t01 = fma2(xs.x, sn01[j], mul2(xc.x, sc01[j]));
            uint64_t t23 = fma2(xs.y, sn23[j], mul2(xc.y, sc23[j]));
            p[j] = mul2(t01, t23);           // (t0*t2, t1*t3) per col
        }

        // out_j = p[j].lo * p[j].hi, two columns at a time
        float p0l, p0h, p1l, p1h, p2l, p2h, p3l, p3h;
        upk2(p[0], p0l, p0h); upk2(p[1], p1l, p1h);
        upk2(p[2], p2l, p2h); upk2(p[3], p3l, p3h);
        ulonglong2 o;
        o.x = abs2(mul2(pk2(p0l, p1l), pk2(p0h, p1h)));   // (out0, out1)
        o.y = abs2(mul2(pk2(p2l, p3l), pk2(p2h, p3h)));   // (out2, out3)

        *reinterpret_cast<ulonglong2*>(orow + (size_t)i * NS) = o;  // STG.128
    }
}

extern "C" void kernel_launch(void* const* d_in, const int* in_sizes, int n_in,
                              void* d_out, int out_size) {
    const float* x  = (const float*)d_in[0];
    const float* sv = (const float*)d_in[1];
    float* out = (float*)d_out;

    dim3 grid(NS / 256, NB / 64);   // 16 x 64 = 1024 blocks
    qk_fused_kernel<<<grid, 256>>>(x, sv, out);
}

// round 5
// speedup vs baseline: 1.1577x; 1.1577x over previous
#include <cuda_runtime.h>
#include <cuda_bf16.h>
#include <cstdint>

// out[b,s] = | prod_k cos((x[b,k]-sv[s,k])/2) |  =  | P12 * P34 |
// P12 = 1/2 [ cos((u+ - v+)/2) + cos((u- - v-)/2) ],  u± = x0±x1, v± = s0±s1
// each cos((u-v)/2) = cos(u/2)cos(v/2) + sin(u/2)sin(v/2)
// -> P12 is a 4-term dot product of row features vs col features (1/2 folded
//    into the row side). Same for P34 with x2,x3 / s2,s3.
#define NB 4096
#define NS 4096

__device__ __forceinline__ uint64_t mul2(uint64_t a, uint64_t b) {
    uint64_t r; asm("mul.rn.f32x2 %0, %1, %2;" : "=l"(r) : "l"(a), "l"(b)); return r;
}
__device__ __forceinline__ uint64_t fma2(uint64_t a, uint64_t b, uint64_t c) {
    uint64_t r; asm("fma.rn.f32x2 %0, %1, %2, %3;" : "=l"(r) : "l"(a), "l"(b), "l"(c)); return r;
}
__device__ __forceinline__ uint64_t abs2(uint64_t v) {
    asm("and.b64 %0, %0, 0x7FFFFFFF7FFFFFFF;" : "+l"(v)); return v;
}
__device__ __forceinline__ uint64_t dup2(float v) {
    uint64_t r; asm("mov.b64 %0, {%1, %1};" : "=l"(r) : "f"(v)); return r;
}

// Block: 64 rows x 256 cols. Thread: 4 cols x 16 rows.
__global__ __launch_bounds__(256, 4) void qk_pair_kernel(
    const float* __restrict__ x,
    const float* __restrict__ sv,
    float* __restrict__ out)
{
    // A (row) features: per row 16 floats = 4 groups of (c,c,s,s) pre-duplicated.
    // Group g in {u+12, u-12, u+34, u-34}; 1/2 scale folded into c and s.
    __shared__ __align__(16) float sxf[64 * 16];   // 4 KB
    // B (col) features: f-major [8][256], f in {C+12,S+12,C-12,S-12,C+34,S+34,C-34,S-34}
    __shared__ __align__(16) float sbf[8 * 256];   // 8 KB

    const int b0 = blockIdx.y << 6;    // 64 rows
    const int s0 = blockIdx.x << 8;    // 256 cols
    const int t  = threadIdx.x;

    // ---- A fill: one sincos/thread. t = row*4 + g ----
    {
        const int g = t & 3;
        float v = x[b0 * 4 + t];                       // coalesced
        float p = __shfl_xor_sync(0xFFFFFFFFu, v, 1);  // partner within (x0,x1)/(x2,x3)
        float u = (g & 1) ? (p - v) : (v + p);         // g even: sum, g odd: diff
        float sn, cs;
        __sincosf(u * 0.5f, &sn, &cs);
        cs *= 0.5f; sn *= 0.5f;                        // fold the 1/2 per pair
        uint64_t* rec = reinterpret_cast<uint64_t*>(sxf) + ((t >> 2) << 3) + (g << 1);
        rec[0] = dup2(cs);
        rec[1] = dup2(sn);
    }

    // ---- B fill: one col per thread, 4 sincos ----
    {
        float4 v = *reinterpret_cast<const float4*>(&sv[(size_t)(s0 + t) * 4]);
        float sn, cs;
        __sincosf((v.x + v.y) * 0.5f, &sn, &cs); sbf[0 * 256 + t] = cs; sbf[1 * 256 + t] = sn;
        __sincosf((v.x - v.y) * 0.5f, &sn, &cs); sbf[2 * 256 + t] = cs; sbf[3 * 256 + t] = sn;
        __sincosf((v.z + v.w) * 0.5f, &sn, &cs); sbf[4 * 256 + t] = cs; sbf[5 * 256 + t] = sn;
        __sincosf((v.z - v.w) * 0.5f, &sn, &cs); sbf[6 * 256 + t] = cs; sbf[7 * 256 + t] = sn;
    }
    __syncthreads();

    const int cg = t & 63;   // 4 cols starting at s0 + 4*cg
    const int rg = t >> 6;   // 16 rows starting at b0 + 16*rg (warp-uniform)

    // ---- hoist B features: 8 coalesced LDS.128; .x=(c0,c1) pack, .y=(c2,c3) ----
    ulonglong2 B[8];
#pragma unroll
    for (int f = 0; f < 8; f++)
        B[f] = *reinterpret_cast<const ulonglong2*>(&sbf[f * 256 + (cg << 2)]);

    float* orow = out + (size_t)(b0 + (rg << 4)) * NS + (s0 + (cg << 2));

#pragma unroll 4
    for (int i = 0; i < 16; i++) {
        const ulonglong2* arec = reinterpret_cast<const ulonglong2*>(
            &sxf[(((rg << 4) + i) << 4)]);          // warp-broadcast loads
        ulonglong2 q0 = arec[0];   // {c+12 dup, s+12 dup}
        ulonglong2 q1 = arec[1];   // {c-12 dup, s-12 dup}
        ulonglong2 q2 = arec[2];   // {c+34 dup, s+34 dup}
        ulonglong2 q3 = arec[3];   // {c-34 dup, s-34 dup}

        // colpair 0 (cols 0,1)
        uint64_t p12a = fma2(q1.y, B[3].x, fma2(q1.x, B[2].x,
                        fma2(q0.y, B[1].x, mul2(q0.x, B[0].x))));
        uint64_t p34a = fma2(q3.y, B[7].x, fma2(q3.x, B[6].x,
                        fma2(q2.y, B[5].x, mul2(q2.x, B[4].x))));
        // colpair 1 (cols 2,3)
        uint64_t p12b = fma2(q1.y, B[3].y, fma2(q1.x, B[2].y,
                        fma2(q0.y, B[1].y, mul2(q0.x, B[0].y))));
        uint64_t p34b = fma2(q3.y, B[7].y, fma2(q3.x, B[6].y,
                        fma2(q2.y, B[5].y, mul2(q2.x, B[4].y))));

        ulonglong2 o;
        o.x = abs2(mul2(p12a, p34a));
        o.y = abs2(mul2(p12b, p34b));
        *reinterpret_cast<ulonglong2*>(orow + (size_t)i * NS) = o;  // STG.128
    }
}

extern "C" void kernel_launch(void* const* d_in, const int* in_sizes, int n_in,
                              void* d_out, int out_size) {
    const float* x  = (const float*)d_in[0];
    const float* sv = (const float*)d_in[1];
    float* out = (float*)d_out;

    dim3 grid(NS / 256, NB / 64);   // 16 x 64 = 1024 blocks
    qk_pair_kernel<<<grid, 256>>>(x, sv, out);
}